// round 7
// baseline (speedup 1.0000x reference)
#include <cuda_runtime.h>
#include <cuda_fp16.h>
#include <math.h>
#include <stddef.h>
#include <stdint.h>

// ---------------------------------------------------------------------------
// NeuralODE via fp16 mma.sync GEMM, CTA tile 128x256, warp tile 64x64.
// 120 GEMMs of [8192x1024]x[1024x1024]; epilogues fuse tanh / RK4 combines
// and emit the next GEMM's fp16 activations directly.
// ---------------------------------------------------------------------------

#define MDIM 8192
#define NDIM 1024
#define KDIM 1024
#define STEPS_N 10

enum EpiMode { EPI_TANH = 0, EPI_K1 = 1, EPI_KMID = 2, EPI_K4 = 3 };

constexpr int BM = 128, BN = 256, BK = 32;
constexpr int NT = 256;
constexpr int NSTAGES = KDIM / BK;  // 32
constexpr int NBUF = 3;

// smem: rows x 32 fp16, row stride 80 B (16*5 -> conflict-free ldmatrix)
constexpr int RSB = 80;
constexpr int TILE_A_B = BM * RSB;          // 10240
constexpr int TILE_B_B = BN * RSB;          // 20480
constexpr int T_A = 0, T_B = TILE_A_B;
constexpr int STAGE_B = TILE_A_B + TILE_B_B;  // 30720
constexpr int SMEM_TOTAL = NBUF * STAGE_B;    // 92160

// ---- global scratch ------------------------------------------------------
__device__ float g_f32[2ull * MDIM * NDIM];           // gh, ksum
__device__ unsigned short g_bf[4ull * MDIM * NDIM];   // hs, gx, y1, y2 (fp16)
__device__ unsigned short g_wt[3ull * KDIM * NDIM];   // w1..w3 (fp16)

// ---- PTX helpers ---------------------------------------------------------

__device__ __forceinline__ uint32_t smem_to_u32(const void* p) {
    uint32_t a;
    asm("{ .reg .u64 t; cvta.to.shared.u64 t, %1; cvt.u32.u64 %0, t; }"
        : "=r"(a) : "l"(p));
    return a;
}

#define CP_ASYNC16(saddr, gptr)                                   \
    asm volatile("cp.async.cg.shared.global [%0], [%1], 16;" ::   \
                     "r"(saddr), "l"(gptr))
#define CP_COMMIT() asm volatile("cp.async.commit_group;" ::: "memory")
#define CP_WAIT2() asm volatile("cp.async.wait_group 2;" ::: "memory")
#define CP_WAIT1() asm volatile("cp.async.wait_group 1;" ::: "memory")
#define CP_WAIT0() asm volatile("cp.async.wait_group 0;" ::: "memory")

#define LDSM_X4(r0, r1, r2, r3, addr)                                     \
    asm volatile("ldmatrix.sync.aligned.m8n8.x4.shared.b16 "              \
                 "{%0,%1,%2,%3}, [%4];"                                   \
                 : "=r"(r0), "=r"(r1), "=r"(r2), "=r"(r3) : "r"(addr))

#define MMA_F16(D, A, B)                                                   \
    asm volatile("mma.sync.aligned.m16n8k16.row.col.f32.f16.f16.f32 "      \
                 "{%0,%1,%2,%3}, {%4,%5,%6,%7}, {%8,%9}, {%0,%1,%2,%3};"   \
                 : "+f"((D)[0]), "+f"((D)[1]), "+f"((D)[2]), "+f"((D)[3])  \
                 : "r"((A)[0]), "r"((A)[1]), "r"((A)[2]), "r"((A)[3]),     \
                   "r"((B)[0]), "r"((B)[1]))

__device__ __forceinline__ float fast_tanh(float x) {
    float r;
    asm("tanh.approx.f32 %0, %1;" : "=f"(r) : "f"(x));
    return r;
}

__device__ __forceinline__ float4 ld4(const float* p) { return *(const float4*)p; }

__device__ __forceinline__ uint32_t pack_h2(float a, float b) {
    __half2 h = __floats2half2_rn(a, b);
    return *(uint32_t*)&h;
}

// ---- weight convert+transpose: out[n][k] = fp16(W[k][n]) -----------------

__global__ void wsplit_kernel(const float* __restrict__ W,
                              unsigned short* __restrict__ hi) {
    __shared__ float t[32][33];
    const int tx = threadIdx.x, ty = threadIdx.y;
    const int n0 = blockIdx.x * 32, k0 = blockIdx.y * 32;
#pragma unroll
    for (int j = 0; j < 32; j += 8)
        t[ty + j][tx] = W[(size_t)(k0 + ty + j) * NDIM + n0 + tx];
    __syncthreads();
#pragma unroll
    for (int j = 0; j < 32; j += 8) {
        float v = t[tx][ty + j];
        __half h = __float2half_rn(v);
        hi[(size_t)(n0 + ty + j) * KDIM + k0 + tx] = *(unsigned short*)&h;
    }
}

// ---- activation convert (h0 prologue) ------------------------------------

__global__ void asplit_kernel(const float* __restrict__ X,
                              unsigned short* __restrict__ hi) {
    size_t i = ((size_t)blockIdx.x * blockDim.x + threadIdx.x) * 4;
    float4 v = ld4(X + i);
    *(uint2*)(hi + i) = make_uint2(pack_h2(v.x, v.y), pack_h2(v.z, v.w));
}

// ---- fused epilogue per (row, col-pair) ----------------------------------

template <int EPI>
__device__ __forceinline__ void epi_rc(int m, int c, float v0, float v1,
                                       unsigned short* oh,
                                       const float* hbase, float* ksum,
                                       float* hout, float coef) {
    const size_t idx = (size_t)m * NDIM + c;
    if (EPI == EPI_TANH) {
        *(uint32_t*)(oh + idx) = pack_h2(fast_tanh(v0), fast_tanh(v1));
    } else if (EPI == EPI_K1) {
        *(float2*)(ksum + idx) = make_float2(v0, v1);
        float2 h = *(const float2*)(hbase + idx);
        *(uint32_t*)(oh + idx) =
            pack_h2(fmaf(coef, v0, h.x), fmaf(coef, v1, h.y));
    } else if (EPI == EPI_KMID) {
        float2 s = *(float2*)(ksum + idx);
        s.x = fmaf(2.f, v0, s.x);
        s.y = fmaf(2.f, v1, s.y);
        *(float2*)(ksum + idx) = s;
        float2 h = *(const float2*)(hbase + idx);
        *(uint32_t*)(oh + idx) =
            pack_h2(fmaf(coef, v0, h.x), fmaf(coef, v1, h.y));
    } else {  // EPI_K4
        float2 s = *(const float2*)(ksum + idx);
        float2 h = *(const float2*)(hbase + idx);
        float g0 = fmaf(coef, s.x + v0, h.x);
        float g1 = fmaf(coef, s.y + v1, h.y);
        *(float2*)(hout + idx) = make_float2(g0, g1);
        *(uint32_t*)(oh + idx) = pack_h2(g0, g1);
    }
}

// ---- main GEMM -----------------------------------------------------------

template <int EPI>
__global__ void __launch_bounds__(NT, 1)
ngemm_kernel(const unsigned short* __restrict__ Ax,
             const unsigned short* __restrict__ Bx,
             const float* __restrict__ bias,
             const float* __restrict__ trow, float tval,
             unsigned short* __restrict__ oh,
             const float* __restrict__ hbase, float* __restrict__ ksum,
             float* __restrict__ hout, float coef) {
    extern __shared__ char smc[];
    const uint32_t sb = smem_to_u32(smc);
    const int tid = threadIdx.x;
    const int lane = tid & 31;
    const int w = tid >> 5;
    const int wm = w & 1;        // 2 x 64 rows
    const int wn = w >> 1;       // 4 x 64 cols
    const int bm = blockIdx.y * BM;
    const int bn = blockIdx.x * BN;

    // cp.async mapping: per thread row tid>>2, 16B chunk (tid&3)
    const int cr = tid >> 2;              // 0..63
    const int cc = (tid & 3) * 8;         // fp16 offset within row
    const unsigned short* ga0 = Ax + (size_t)(bm + cr) * KDIM + cc;
    const unsigned short* ga1 = Ax + (size_t)(bm + 64 + cr) * KDIM + cc;
    const unsigned short* gb0 = Bx + (size_t)(bn + cr) * KDIM + cc;
    const unsigned short* gb1 = Bx + (size_t)(bn + 64 + cr) * KDIM + cc;
    const unsigned short* gb2 = Bx + (size_t)(bn + 128 + cr) * KDIM + cc;
    const unsigned short* gb3 = Bx + (size_t)(bn + 192 + cr) * KDIM + cc;
    const uint32_t sA0 = (uint32_t)(cr * RSB + (tid & 3) * 16);
    const uint32_t sA1 = sA0 + 64 * RSB;

    const uint32_t a_off = (uint32_t)((lane & 15) * RSB + ((lane & 16) ? 16 : 0));
    const uint32_t b_off = (uint32_t)(((lane & 7) + ((lane & 16) ? 8 : 0)) * RSB +
                                      ((lane & 8) ? 16 : 0));

    float acc[4][8][4];
#pragma unroll
    for (int i = 0; i < 4; i++)
#pragma unroll
        for (int j = 0; j < 8; j++)
#pragma unroll
            for (int q = 0; q < 4; q++) acc[i][j][q] = 0.f;

#define ISSUE_STAGE(st)                                                   \
    do {                                                                  \
        const int _kc = (st) * BK;                                        \
        const uint32_t _b = sb + ((st) % NBUF) * STAGE_B;                 \
        CP_ASYNC16(_b + T_A + sA0, ga0 + _kc);                            \
        CP_ASYNC16(_b + T_A + sA1, ga1 + _kc);                            \
        CP_ASYNC16(_b + T_B + sA0, gb0 + _kc);                            \
        CP_ASYNC16(_b + T_B + sA0 + 64 * RSB, gb1 + _kc);                 \
        CP_ASYNC16(_b + T_B + sA0 + 128 * RSB, gb2 + _kc);                \
        CP_ASYNC16(_b + T_B + sA0 + 192 * RSB, gb3 + _kc);                \
        CP_COMMIT();                                                      \
    } while (0)

    ISSUE_STAGE(0);
    ISSUE_STAGE(1);

#pragma unroll 1
    for (int s = 0; s < NSTAGES; ++s) {
        __syncthreads();  // all warps done with the buffer being refilled
        if (s + 2 < NSTAGES) {
            ISSUE_STAGE(s + 2);
            CP_WAIT2();
        } else if (s + 1 < NSTAGES) {
            CP_WAIT1();
        } else {
            CP_WAIT0();
        }
        __syncthreads();

        const uint32_t base = sb + (s % NBUF) * STAGE_B;
#pragma unroll
        for (int ks = 0; ks < 2; ++ks) {
            uint32_t a_[4][4], b_[8][2];
#pragma unroll
            for (int i = 0; i < 4; ++i) {
                const uint32_t ra =
                    base + T_A +
                    (uint32_t)((wm * 64 + i * 16) * RSB + ks * 32) + a_off;
                LDSM_X4(a_[i][0], a_[i][1], a_[i][2], a_[i][3], ra);
            }
#pragma unroll
            for (int jj = 0; jj < 4; ++jj) {
                const uint32_t rb =
                    base + T_B +
                    (uint32_t)((wn * 64 + jj * 16) * RSB + ks * 32) + b_off;
                uint32_t t0, t1, t2, t3;
                LDSM_X4(t0, t1, t2, t3, rb);
                b_[2 * jj][0] = t0; b_[2 * jj][1] = t1;
                b_[2 * jj + 1][0] = t2; b_[2 * jj + 1][1] = t3;
            }
#pragma unroll
            for (int i = 0; i < 4; ++i)
#pragma unroll
                for (int j = 0; j < 8; ++j) {
                    MMA_F16(acc[i][j], a_[i], b_[j]);
                }
        }
    }
#undef ISSUE_STAGE

    // ---------------- epilogue -------------------------------------------
#pragma unroll
    for (int j = 0; j < 8; ++j) {
        const int c = bn + wn * 64 + j * 8 + (lane & 3) * 2;
        float bb0 = bias[c], bb1 = bias[c + 1];
        if (EPI == EPI_TANH && trow != nullptr) {
            bb0 = fmaf(tval, trow[c], bb0);
            bb1 = fmaf(tval, trow[c + 1], bb1);
        }
#pragma unroll
        for (int i = 0; i < 4; ++i) {
            const int m0 = bm + wm * 64 + i * 16 + (lane >> 2);
            epi_rc<EPI>(m0, c, acc[i][j][0] + bb0, acc[i][j][1] + bb1,
                        oh, hbase, ksum, hout, coef);
            epi_rc<EPI>(m0 + 8, c, acc[i][j][2] + bb0, acc[i][j][3] + bb1,
                        oh, hbase, ksum, hout, coef);
        }
    }
}

// ---------------------------------------------------------------------------

template <int EPI>
static inline void launch_gemm(const unsigned short* Ax, const unsigned short* Bx,
                               const float* bias, const float* trow, float tval,
                               unsigned short* oh, const float* hbase,
                               float* ksum, float* hout, float coef) {
    dim3 grid(NDIM / BN, MDIM / BM);
    ngemm_kernel<EPI><<<grid, NT, SMEM_TOTAL>>>(Ax, Bx, bias, trow, tval,
                                                oh, hbase, ksum, hout, coef);
}

extern "C" void kernel_launch(void* const* d_in, const int* in_sizes, int n_in,
                              void* d_out, int out_size) {
    const float* h0 = (const float*)d_in[0];
    const float* W1 = (const float*)d_in[1];
    const float* b1 = (const float*)d_in[2];
    const float* W2 = (const float*)d_in[3];
    const float* b2 = (const float*)d_in[4];
    const float* W3 = (const float*)d_in[5];
    const float* b3 = (const float*)d_in[6];
    float* out = (float*)d_out;

    cudaFuncSetAttribute(ngemm_kernel<EPI_TANH>,
                         cudaFuncAttributeMaxDynamicSharedMemorySize, SMEM_TOTAL);
    cudaFuncSetAttribute(ngemm_kernel<EPI_K1>,
                         cudaFuncAttributeMaxDynamicSharedMemorySize, SMEM_TOTAL);
    cudaFuncSetAttribute(ngemm_kernel<EPI_KMID>,
                         cudaFuncAttributeMaxDynamicSharedMemorySize, SMEM_TOTAL);
    cudaFuncSetAttribute(ngemm_kernel<EPI_K4>,
                         cudaFuncAttributeMaxDynamicSharedMemorySize, SMEM_TOTAL);

    float* fbase = nullptr;
    cudaGetSymbolAddress((void**)&fbase, g_f32);
    unsigned short* abase = nullptr;
    cudaGetSymbolAddress((void**)&abase, g_bf);
    unsigned short* wbase = nullptr;
    cudaGetSymbolAddress((void**)&wbase, g_wt);

    const size_t SZ = (size_t)MDIM * NDIM;
    float* gh = fbase;
    float* ks = fbase + SZ;

    unsigned short* hs = abase;            // h as fp16
    unsigned short* gx = abase + SZ;       // dynamics input fp16
    unsigned short* y1 = abase + 2 * SZ;
    unsigned short* y2 = abase + 3 * SZ;

    const size_t WSZ = (size_t)KDIM * NDIM;
    unsigned short* w1x = wbase;
    unsigned short* w2x = wbase + WSZ;
    unsigned short* w3x = wbase + 2 * WSZ;

    {
        dim3 g(NDIM / 32, KDIM / 32), b(32, 8);
        wsplit_kernel<<<g, b>>>(W1, w1x);
        wsplit_kernel<<<g, b>>>(W2, w2x);
        wsplit_kernel<<<g, b>>>(W3, w3x);
        asplit_kernel<<<(int)(SZ / 4 / 256), 256>>>(h0, hs);
    }

    const float dt = 0.1f;
    const float* trow = W1 + (size_t)KDIM * NDIM;  // W1 row 1024 (t row)

    for (int s = 0; s < STEPS_N; s++) {
        const float t0 = dt * (float)s;
        const float* hin = (s == 0) ? h0 : gh;
        float* hdst = (s == STEPS_N - 1) ? out : gh;

        // k1 = f(t0, h)
        launch_gemm<EPI_TANH>(hs, w1x, b1, trow, t0, y1, nullptr, nullptr, nullptr, 0.f);
        launch_gemm<EPI_TANH>(y1, w2x, b2, nullptr, 0.f, y2, nullptr, nullptr, nullptr, 0.f);
        launch_gemm<EPI_K1>(y2, w3x, b3, nullptr, 0.f, gx, hin, ks, nullptr, dt * 0.5f);
        // k2
        launch_gemm<EPI_TANH>(gx, w1x, b1, trow, t0 + dt * 0.5f, y1, nullptr, nullptr, nullptr, 0.f);
        launch_gemm<EPI_TANH>(y1, w2x, b2, nullptr, 0.f, y2, nullptr, nullptr, nullptr, 0.f);
        launch_gemm<EPI_KMID>(y2, w3x, b3, nullptr, 0.f, gx, hin, ks, nullptr, dt * 0.5f);
        // k3
        launch_gemm<EPI_TANH>(gx, w1x, b1, trow, t0 + dt * 0.5f, y1, nullptr, nullptr, nullptr, 0.f);
        launch_gemm<EPI_TANH>(y1, w2x, b2, nullptr, 0.f, y2, nullptr, nullptr, nullptr, 0.f);
        launch_gemm<EPI_KMID>(y2, w3x, b3, nullptr, 0.f, gx, hin, ks, nullptr, dt);
        // k4 + combine
        launch_gemm<EPI_TANH>(gx, w1x, b1, trow, t0 + dt, y1, nullptr, nullptr, nullptr, 0.f);
        launch_gemm<EPI_TANH>(y1, w2x, b2, nullptr, 0.f, y2, nullptr, nullptr, nullptr, 0.f);
        launch_gemm<EPI_K4>(y2, w3x, b3, nullptr, 0.f, hs, hin, ks, hdst, dt / 6.0f);
    }
}

// round 8
// speedup vs baseline: 1.1722x; 1.1722x over previous
#include <cuda_runtime.h>
#include <cuda_fp16.h>
#include <math.h>
#include <stddef.h>
#include <stdint.h>

// ---------------------------------------------------------------------------
// NeuralODE via fp16 mma.sync GEMM. CTA tile 128x128 (R6 config), BK=32,
// NBUF=4, single __syncthreads per stage, 2 CTAs resident per SM.
// 120 GEMMs of [8192x1024]x[1024x1024]; epilogues fuse tanh / RK4 combines
// and emit the next GEMM's fp16 activations directly.
// ---------------------------------------------------------------------------

#define MDIM 8192
#define NDIM 1024
#define KDIM 1024
#define STEPS_N 10

enum EpiMode { EPI_TANH = 0, EPI_K1 = 1, EPI_KMID = 2, EPI_K4 = 3 };

constexpr int BM = 128, BN = 128, BK = 32;
constexpr int NT = 256;
constexpr int NSTAGES = KDIM / BK;  // 32
constexpr int NBUF = 4;

// smem tile: 128 rows x 32 fp16, row stride 80 B (16*5, conflict-free ldsm)
constexpr int RSB = 80;
constexpr int TILE_B = 128 * RSB;          // 10240
constexpr int T_A = 0, T_B = TILE_B;
constexpr int STAGE_B = 2 * TILE_B;        // 20480
constexpr int SMEM_TOTAL = NBUF * STAGE_B; // 81920  (2 CTAs -> 160KB/SM)

// ---- global scratch ------------------------------------------------------
__device__ float g_f32[2ull * MDIM * NDIM];           // gh, ksum
__device__ unsigned short g_bf[4ull * MDIM * NDIM];   // hs, gx, y1, y2 (fp16)
__device__ unsigned short g_wt[3ull * KDIM * NDIM];   // w1..w3 (fp16)

// ---- PTX helpers ---------------------------------------------------------

__device__ __forceinline__ uint32_t smem_to_u32(const void* p) {
    uint32_t a;
    asm("{ .reg .u64 t; cvta.to.shared.u64 t, %1; cvt.u32.u64 %0, t; }"
        : "=r"(a) : "l"(p));
    return a;
}

#define CP_ASYNC16(saddr, gptr)                                   \
    asm volatile("cp.async.cg.shared.global [%0], [%1], 16;" ::   \
                     "r"(saddr), "l"(gptr))
#define CP_COMMIT() asm volatile("cp.async.commit_group;" ::: "memory")
#define CP_WAIT2() asm volatile("cp.async.wait_group 2;" ::: "memory")
#define CP_WAIT1() asm volatile("cp.async.wait_group 1;" ::: "memory")
#define CP_WAIT0() asm volatile("cp.async.wait_group 0;" ::: "memory")

#define LDSM_X4(r0, r1, r2, r3, addr)                                     \
    asm volatile("ldmatrix.sync.aligned.m8n8.x4.shared.b16 "              \
                 "{%0,%1,%2,%3}, [%4];"                                   \
                 : "=r"(r0), "=r"(r1), "=r"(r2), "=r"(r3) : "r"(addr))

#define MMA_F16(D, A, B)                                                   \
    asm volatile("mma.sync.aligned.m16n8k16.row.col.f32.f16.f16.f32 "      \
                 "{%0,%1,%2,%3}, {%4,%5,%6,%7}, {%8,%9}, {%0,%1,%2,%3};"   \
                 : "+f"((D)[0]), "+f"((D)[1]), "+f"((D)[2]), "+f"((D)[3])  \
                 : "r"((A)[0]), "r"((A)[1]), "r"((A)[2]), "r"((A)[3]),     \
                   "r"((B)[0]), "r"((B)[1]))

__device__ __forceinline__ float fast_tanh(float x) {
    float r;
    asm("tanh.approx.f32 %0, %1;" : "=f"(r) : "f"(x));
    return r;
}

__device__ __forceinline__ float4 ld4(const float* p) { return *(const float4*)p; }

__device__ __forceinline__ uint32_t pack_h2(float a, float b) {
    __half2 h = __floats2half2_rn(a, b);
    return *(uint32_t*)&h;
}

// ---- weight convert+transpose: out[n][k] = fp16(W[k][n]) -----------------

__global__ void wsplit_kernel(const float* __restrict__ W,
                              unsigned short* __restrict__ hi) {
    __shared__ float t[32][33];
    const int tx = threadIdx.x, ty = threadIdx.y;
    const int n0 = blockIdx.x * 32, k0 = blockIdx.y * 32;
#pragma unroll
    for (int j = 0; j < 32; j += 8)
        t[ty + j][tx] = W[(size_t)(k0 + ty + j) * NDIM + n0 + tx];
    __syncthreads();
#pragma unroll
    for (int j = 0; j < 32; j += 8) {
        float v = t[tx][ty + j];
        __half h = __float2half_rn(v);
        hi[(size_t)(n0 + ty + j) * KDIM + k0 + tx] = *(unsigned short*)&h;
    }
}

// ---- activation convert (h0 prologue) ------------------------------------

__global__ void asplit_kernel(const float* __restrict__ X,
                              unsigned short* __restrict__ hi) {
    size_t i = ((size_t)blockIdx.x * blockDim.x + threadIdx.x) * 4;
    float4 v = ld4(X + i);
    *(uint2*)(hi + i) = make_uint2(pack_h2(v.x, v.y), pack_h2(v.z, v.w));
}

// ---- fused epilogue per (row, col-pair) ----------------------------------

template <int EPI>
__device__ __forceinline__ void epi_rc(int m, int c, float v0, float v1,
                                       unsigned short* oh,
                                       const float* hbase, float* ksum,
                                       float* hout, float coef) {
    const size_t idx = (size_t)m * NDIM + c;
    if (EPI == EPI_TANH) {
        *(uint32_t*)(oh + idx) = pack_h2(fast_tanh(v0), fast_tanh(v1));
    } else if (EPI == EPI_K1) {
        *(float2*)(ksum + idx) = make_float2(v0, v1);
        float2 h = *(const float2*)(hbase + idx);
        *(uint32_t*)(oh + idx) =
            pack_h2(fmaf(coef, v0, h.x), fmaf(coef, v1, h.y));
    } else if (EPI == EPI_KMID) {
        float2 s = *(float2*)(ksum + idx);
        s.x = fmaf(2.f, v0, s.x);
        s.y = fmaf(2.f, v1, s.y);
        *(float2*)(ksum + idx) = s;
        float2 h = *(const float2*)(hbase + idx);
        *(uint32_t*)(oh + idx) =
            pack_h2(fmaf(coef, v0, h.x), fmaf(coef, v1, h.y));
    } else {  // EPI_K4
        float2 s = *(const float2*)(ksum + idx);
        float2 h = *(const float2*)(hbase + idx);
        float g0 = fmaf(coef, s.x + v0, h.x);
        float g1 = fmaf(coef, s.y + v1, h.y);
        *(float2*)(hout + idx) = make_float2(g0, g1);
        *(uint32_t*)(oh + idx) = pack_h2(g0, g1);
    }
}

// ---- main GEMM -----------------------------------------------------------

template <int EPI>
__global__ void __launch_bounds__(NT, 2)
ngemm_kernel(const unsigned short* __restrict__ Ax,
             const unsigned short* __restrict__ Bx,
             const float* __restrict__ bias,
             const float* __restrict__ trow, float tval,
             unsigned short* __restrict__ oh,
             const float* __restrict__ hbase, float* __restrict__ ksum,
             float* __restrict__ hout, float coef) {
    extern __shared__ char smc[];
    const uint32_t sb = smem_to_u32(smc);
    const int tid = threadIdx.x;
    const int lane = tid & 31;
    const int w = tid >> 5;
    const int wm = w & 1;
    const int wn = w >> 1;
    const int bm = blockIdx.y * BM;
    const int bn = blockIdx.x * BN;

    // cp.async chunk mapping: 512 x 16B chunks per tile, 2 per thread
    const int ch0 = tid, ch1 = tid + NT;
    const int r0 = ch0 >> 2, e0 = (ch0 & 3) * 8;
    const int r1 = ch1 >> 2, e1 = (ch1 & 3) * 8;
    const unsigned short* ga0 = Ax + (size_t)(bm + r0) * KDIM + e0;
    const unsigned short* ga1 = Ax + (size_t)(bm + r1) * KDIM + e1;
    const unsigned short* gb0 = Bx + (size_t)(bn + r0) * KDIM + e0;
    const unsigned short* gb1 = Bx + (size_t)(bn + r1) * KDIM + e1;
    const uint32_t s0 = (uint32_t)(r0 * RSB + (ch0 & 3) * 16);
    const uint32_t s1 = (uint32_t)(r1 * RSB + (ch1 & 3) * 16);

    const uint32_t a_off = (uint32_t)((lane & 15) * RSB + ((lane & 16) ? 16 : 0));
    const uint32_t b_off = (uint32_t)(((lane & 7) + ((lane & 16) ? 8 : 0)) * RSB +
                                      ((lane & 8) ? 16 : 0));

    float acc[4][4][4];
#pragma unroll
    for (int i = 0; i < 4; i++)
#pragma unroll
        for (int j = 0; j < 4; j++)
#pragma unroll
            for (int q = 0; q < 4; q++) acc[i][j][q] = 0.f;

#define ISSUE_STAGE(st)                                                   \
    do {                                                                  \
        const int _kc = (st) * BK;                                        \
        const uint32_t _b = sb + ((st) % NBUF) * STAGE_B;                 \
        CP_ASYNC16(_b + T_A + s0, ga0 + _kc);                             \
        CP_ASYNC16(_b + T_A + s1, ga1 + _kc);                             \
        CP_ASYNC16(_b + T_B + s0, gb0 + _kc);                             \
        CP_ASYNC16(_b + T_B + s1, gb1 + _kc);                             \
        CP_COMMIT();                                                      \
    } while (0)

    ISSUE_STAGE(0);
    ISSUE_STAGE(1);
    ISSUE_STAGE(2);

#pragma unroll 1
    for (int s = 0; s < NSTAGES; ++s) {
        // Ensure group s is complete. Pending groups at this point are a
        // subset of {s, s+1, s+2} (the issue of s+3 happens after the wait),
        // so allow (last_issued - s) pending.
        if (s + 2 < NSTAGES) {
            CP_WAIT2();
        } else if (s + 1 < NSTAGES) {
            CP_WAIT1();
        } else {
            CP_WAIT0();
        }
        // Single barrier: makes stage-s data visible to all warps AND
        // guarantees everyone finished reading buffer (s-1)%NBUF (consumed in
        // stage s-1, before this barrier) so ISSUE(s+3) may overwrite it.
        __syncthreads();
        if (s + 3 < NSTAGES) ISSUE_STAGE(s + 3);

        const uint32_t base = sb + (s % NBUF) * STAGE_B;
#pragma unroll
        for (int ks = 0; ks < 2; ++ks) {
            uint32_t a_[4][4], b_[4][2];
#pragma unroll
            for (int i = 0; i < 4; ++i) {
                const uint32_t ra =
                    base + (uint32_t)((wm * 64 + i * 16) * RSB + ks * 32) + a_off;
                LDSM_X4(a_[i][0], a_[i][1], a_[i][2], a_[i][3], ra + T_A);
            }
#pragma unroll
            for (int jj = 0; jj < 2; ++jj) {
                const uint32_t rb =
                    base + (uint32_t)((wn * 32 + jj * 16) * RSB + ks * 32) + b_off;
                uint32_t t0, t1, t2, t3;
                LDSM_X4(t0, t1, t2, t3, rb + T_B);
                b_[2 * jj][0] = t0; b_[2 * jj][1] = t1;
                b_[2 * jj + 1][0] = t2; b_[2 * jj + 1][1] = t3;
            }
#pragma unroll
            for (int i = 0; i < 4; ++i)
#pragma unroll
                for (int j = 0; j < 4; ++j) {
                    MMA_F16(acc[i][j], a_[i], b_[j]);
                }
        }
    }
#undef ISSUE_STAGE

    // ---------------- epilogue -------------------------------------------
#pragma unroll
    for (int j = 0; j < 4; ++j) {
        const int c = bn + wn * 32 + j * 8 + (lane & 3) * 2;
        float bb0 = bias[c], bb1 = bias[c + 1];
        if (EPI == EPI_TANH && trow != nullptr) {
            bb0 = fmaf(tval, trow[c], bb0);
            bb1 = fmaf(tval, trow[c + 1], bb1);
        }
#pragma unroll
        for (int i = 0; i < 4; ++i) {
            const int m0 = bm + wm * 64 + i * 16 + (lane >> 2);
            epi_rc<EPI>(m0, c, acc[i][j][0] + bb0, acc[i][j][1] + bb1,
                        oh, hbase, ksum, hout, coef);
            epi_rc<EPI>(m0 + 8, c, acc[i][j][2] + bb0, acc[i][j][3] + bb1,
                        oh, hbase, ksum, hout, coef);
        }
    }
}

// ---------------------------------------------------------------------------

template <int EPI>
static inline void launch_gemm(const unsigned short* Ax, const unsigned short* Bx,
                               const float* bias, const float* trow, float tval,
                               unsigned short* oh, const float* hbase,
                               float* ksum, float* hout, float coef) {
    dim3 grid(NDIM / BN, MDIM / BM);
    ngemm_kernel<EPI><<<grid, NT, SMEM_TOTAL>>>(Ax, Bx, bias, trow, tval,
                                                oh, hbase, ksum, hout, coef);
}

extern "C" void kernel_launch(void* const* d_in, const int* in_sizes, int n_in,
                              void* d_out, int out_size) {
    const float* h0 = (const float*)d_in[0];
    const float* W1 = (const float*)d_in[1];
    const float* b1 = (const float*)d_in[2];
    const float* W2 = (const float*)d_in[3];
    const float* b2 = (const float*)d_in[4];
    const float* W3 = (const float*)d_in[5];
    const float* b3 = (const float*)d_in[6];
    float* out = (float*)d_out;

    cudaFuncSetAttribute(ngemm_kernel<EPI_TANH>,
                         cudaFuncAttributeMaxDynamicSharedMemorySize, SMEM_TOTAL);
    cudaFuncSetAttribute(ngemm_kernel<EPI_K1>,
                         cudaFuncAttributeMaxDynamicSharedMemorySize, SMEM_TOTAL);
    cudaFuncSetAttribute(ngemm_kernel<EPI_KMID>,
                         cudaFuncAttributeMaxDynamicSharedMemorySize, SMEM_TOTAL);
    cudaFuncSetAttribute(ngemm_kernel<EPI_K4>,
                         cudaFuncAttributeMaxDynamicSharedMemorySize, SMEM_TOTAL);

    float* fbase = nullptr;
    cudaGetSymbolAddress((void**)&fbase, g_f32);
    unsigned short* abase = nullptr;
    cudaGetSymbolAddress((void**)&abase, g_bf);
    unsigned short* wbase = nullptr;
    cudaGetSymbolAddress((void**)&wbase, g_wt);

    const size_t SZ = (size_t)MDIM * NDIM;
    float* gh = fbase;
    float* ks = fbase + SZ;

    unsigned short* hs = abase;            // h as fp16
    unsigned short* gx = abase + SZ;       // dynamics input fp16
    unsigned short* y1 = abase + 2 * SZ;
    unsigned short* y2 = abase + 3 * SZ;

    const size_t WSZ = (size_t)KDIM * NDIM;
    unsigned short* w1x = wbase;
    unsigned short* w2x = wbase + WSZ;
    unsigned short* w3x = wbase + 2 * WSZ;

    {
        dim3 g(NDIM / 32, KDIM / 32), b(32, 8);
        wsplit_kernel<<<g, b>>>(W1, w1x);
        wsplit_kernel<<<g, b>>>(W2, w2x);
        wsplit_kernel<<<g, b>>>(W3, w3x);
        asplit_kernel<<<(int)(SZ / 4 / 256), 256>>>(h0, hs);
    }

    const float dt = 0.1f;
    const float* trow = W1 + (size_t)KDIM * NDIM;  // W1 row 1024 (t row)

    for (int s = 0; s < STEPS_N; s++) {
        const float t0 = dt * (float)s;
        const float* hin = (s == 0) ? h0 : gh;
        float* hdst = (s == STEPS_N - 1) ? out : gh;

        // k1 = f(t0, h)
        launch_gemm<EPI_TANH>(hs, w1x, b1, trow, t0, y1, nullptr, nullptr, nullptr, 0.f);
        launch_gemm<EPI_TANH>(y1, w2x, b2, nullptr, 0.f, y2, nullptr, nullptr, nullptr, 0.f);
        launch_gemm<EPI_K1>(y2, w3x, b3, nullptr, 0.f, gx, hin, ks, nullptr, dt * 0.5f);
        // k2
        launch_gemm<EPI_TANH>(gx, w1x, b1, trow, t0 + dt * 0.5f, y1, nullptr, nullptr, nullptr, 0.f);
        launch_gemm<EPI_TANH>(y1, w2x, b2, nullptr, 0.f, y2, nullptr, nullptr, nullptr, 0.f);
        launch_gemm<EPI_KMID>(y2, w3x, b3, nullptr, 0.f, gx, hin, ks, nullptr, dt * 0.5f);
        // k3
        launch_gemm<EPI_TANH>(gx, w1x, b1, trow, t0 + dt * 0.5f, y1, nullptr, nullptr, nullptr, 0.f);
        launch_gemm<EPI_TANH>(y1, w2x, b2, nullptr, 0.f, y2, nullptr, nullptr, nullptr, 0.f);
        launch_gemm<EPI_KMID>(y2, w3x, b3, nullptr, 0.f, gx, hin, ks, nullptr, dt);
        // k4 + combine
        launch_gemm<EPI_TANH>(gx, w1x, b1, trow, t0 + dt, y1, nullptr, nullptr, nullptr, 0.f);
        launch_gemm<EPI_TANH>(y1, w2x, b2, nullptr, 0.f, y2, nullptr, nullptr, nullptr, 0.f);
        launch_gemm<EPI_K4>(y2, w3x, b3, nullptr, 0.f, hs, hin, ks, hdst, dt / 6.0f);
    }
}